// round 5
// baseline (speedup 1.0000x reference)
#include <cuda_runtime.h>
#include <stdint.h>

#define NN 4096
#define NE 131072
#define EPSV 0.005f
// thetas: 0.4, 0.24, 0.144, 0.0864
#define TH1 0.24f
#define TH2 0.144f
#define TH3 0.0864f

// Scratch (allocation-free rule: __device__ globals)
__device__ float g_A[(size_t)NN * NN];   // dense A, 64 MB
__device__ float g_M2[(size_t)NN * NN];  // thr(A@A), 64 MB
__device__ int   g_is64;                 // 1 if edge_index is int64, 0 if int32

// ---------------------------------------------------------------------------
// Detect index dtype on-device (harness may downcast int64 -> int32).
// If the buffer is int32, an int64 read fuses two entries and is >= 2^32
// unless the odd word is 0 (p ~ 1/4096) -> 256 probes give certainty.
__global__ void detect_kernel(const void* __restrict__ ei) {
    __shared__ int ok;
    if (threadIdx.x == 0) ok = 1;
    __syncthreads();
    long long v = reinterpret_cast<const long long*>(ei)[threadIdx.x];
    if ((unsigned long long)v >= (unsigned long long)NN) ok = 0;  // benign race
    __syncthreads();
    if (threadIdx.x == 0) g_is64 = ok;
}

__device__ __forceinline__ void load_edge(const void* ei, int e, int& s, int& d) {
    if (g_is64) {
        s = (int)reinterpret_cast<const long long*>(ei)[e];
        d = (int)reinterpret_cast<const long long*>(ei)[NE + e];
    } else {
        s = reinterpret_cast<const int*>(ei)[e];
        d = reinterpret_cast<const int*>(ei)[NE + e];
    }
}

// ---------------------------------------------------------------------------
__global__ void zero_A_kernel() {
    size_t i = (size_t)blockIdx.x * blockDim.x + threadIdx.x;  // one float4 each
    reinterpret_cast<float4*>(g_A)[i] = make_float4(0.f, 0.f, 0.f, 0.f);
}

__global__ void scatter_A_kernel(const void* __restrict__ ei,
                                 const float* __restrict__ w) {
    int e = blockIdx.x * blockDim.x + threadIdx.x;
    if (e < NE) {
        int s, d; load_edge(ei, e, s, d);
        if ((unsigned)s < NN && (unsigned)d < NN)
            atomicAdd(&g_A[(size_t)s * NN + d], w[e]);
    }
}

__global__ void scatter_P0_kernel(float* __restrict__ out,
                                  const void* __restrict__ ei) {
    int e = blockIdx.x * blockDim.x + threadIdx.x;
    if (e < NE) {
        int s, d; load_edge(ei, e, s, d);
        if ((unsigned)s < NN && (unsigned)d < NN)
            atomicAdd(&out[(size_t)s * NN + d], 0.4f);  // theta0 per edge
    }
}

// ---------------------------------------------------------------------------
// One CTA per output row. 256 threads; thread t owns float4 column-chunks
// { t, 256+t, 512+t, 768+t } (interleaved -> coalesced).
// MODE 0: g_M2 = thr(A @ g_A)
// MODE 1: OutParam = TH1*A + TH2*M2 + TH3*thr(A @ g_M2)
template <int MODE>
__global__ __launch_bounds__(256, 6)
void spmm_kernel(float* __restrict__ OutParam) {
    __shared__ float          s_val[NN];
    __shared__ unsigned short s_col[NN];
    __shared__ int            s_wsum[8];

    const int row  = blockIdx.x;
    const int t    = threadIdx.x;
    const int lane = t & 31;
    const int wid  = t >> 5;

    const float* __restrict__ Arow = g_A + (size_t)row * NN;
    const float4* __restrict__ row4 = reinterpret_cast<const float4*>(Arow);
    const float* __restrict__ D = (MODE == 0) ? g_A : g_M2;

    // ---- deterministic nonzero compaction (ascending column order) ----
    int base = 0;
    #pragma unroll
    for (int c = 0; c < 4; ++c) {
        float4 v = row4[c * 256 + t];
        int m = (v.x != 0.f) + (v.y != 0.f) + (v.z != 0.f) + (v.w != 0.f);
        // inclusive warp scan
        int incl = m;
        #pragma unroll
        for (int d = 1; d < 32; d <<= 1) {
            int y = __shfl_up_sync(0xffffffffu, incl, d);
            if (lane >= d) incl += y;
        }
        if (lane == 31) s_wsum[wid] = incl;
        __syncthreads();
        int wbase = 0;
        #pragma unroll
        for (int wIt = 0; wIt < 8; ++wIt)
            if (wIt < wid) wbase += s_wsum[wIt];
        int tot = 0;
        #pragma unroll
        for (int wIt = 0; wIt < 8; ++wIt) tot += s_wsum[wIt];

        int pos  = base + wbase + (incl - m);
        int col0 = (c * 256 + t) * 4;
        if (v.x != 0.f) { s_val[pos] = v.x; s_col[pos] = (unsigned short)(col0 + 0); pos++; }
        if (v.y != 0.f) { s_val[pos] = v.y; s_col[pos] = (unsigned short)(col0 + 1); pos++; }
        if (v.z != 0.f) { s_val[pos] = v.z; s_col[pos] = (unsigned short)(col0 + 2); pos++; }
        if (v.w != 0.f) { s_val[pos] = v.w; s_col[pos] = (unsigned short)(col0 + 3); pos++; }
        base += tot;
        __syncthreads();  // protects s_wsum reuse AND publishes s_val/s_col
    }
    const int nnz = base;

    // ---- accumulate: acc[j] += a * D[k, cols(t,j)] ----
    float4 acc0 = make_float4(0.f, 0.f, 0.f, 0.f);
    float4 acc1 = acc0, acc2 = acc0, acc3 = acc0;

    for (int n = 0; n < nnz; ++n) {
        float a = s_val[n];
        int   k = s_col[n];
        const float4* __restrict__ Dk =
            reinterpret_cast<const float4*>(D + (size_t)k * NN);
        float4 v0 = __ldg(&Dk[t]);
        float4 v1 = __ldg(&Dk[256 + t]);
        float4 v2 = __ldg(&Dk[512 + t]);
        float4 v3 = __ldg(&Dk[768 + t]);
        acc0.x += a * v0.x; acc0.y += a * v0.y; acc0.z += a * v0.z; acc0.w += a * v0.w;
        acc1.x += a * v1.x; acc1.y += a * v1.y; acc1.z += a * v1.z; acc1.w += a * v1.w;
        acc2.x += a * v2.x; acc2.y += a * v2.y; acc2.z += a * v2.z; acc2.w += a * v2.w;
        acc3.x += a * v3.x; acc3.y += a * v3.y; acc3.z += a * v3.z; acc3.w += a * v3.w;
    }

    // ---- epilogue ----
    #define THR(x) ((x) >= EPSV ? (x) : 0.f)
    if (MODE == 0) {
        float4* __restrict__ out4 =
            reinterpret_cast<float4*>(g_M2 + (size_t)row * NN);
        float4 r;
        r.x=THR(acc0.x); r.y=THR(acc0.y); r.z=THR(acc0.z); r.w=THR(acc0.w); out4[t]       = r;
        r.x=THR(acc1.x); r.y=THR(acc1.y); r.z=THR(acc1.z); r.w=THR(acc1.w); out4[256 + t] = r;
        r.x=THR(acc2.x); r.y=THR(acc2.y); r.z=THR(acc2.z); r.w=THR(acc2.w); out4[512 + t] = r;
        r.x=THR(acc3.x); r.y=THR(acc3.y); r.z=THR(acc3.z); r.w=THR(acc3.w); out4[768 + t] = r;
    } else {
        float4* __restrict__ out4 =
            reinterpret_cast<float4*>(OutParam + (size_t)row * NN);
        const float4* __restrict__ a4 = row4;
        const float4* __restrict__ m4 =
            reinterpret_cast<const float4*>(g_M2 + (size_t)row * NN);
        #pragma unroll
        for (int j = 0; j < 4; ++j) {
            float4 acc = (j == 0) ? acc0 : (j == 1) ? acc1 : (j == 2) ? acc2 : acc3;
            float4 av = a4[j * 256 + t];
            float4 mv = m4[j * 256 + t];
            float4 r;
            r.x = TH1 * av.x + TH2 * mv.x + TH3 * THR(acc.x);
            r.y = TH1 * av.y + TH2 * mv.y + TH3 * THR(acc.y);
            r.z = TH1 * av.z + TH2 * mv.z + TH3 * THR(acc.z);
            r.w = TH1 * av.w + TH2 * mv.w + TH3 * THR(acc.w);
            out4[j * 256 + t] = r;
        }
    }
    #undef THR
}

// ---------------------------------------------------------------------------
extern "C" void kernel_launch(void* const* d_in, const int* in_sizes, int n_in,
                              void* d_out, int out_size) {
    // Resolve inputs BY ELEMENT COUNT (robust to ordering):
    //   x          : 524288 f32  (unused)
    //   edge_index : 262144 (int64 OR harness-downcast int32)
    //   edge_attr  : 131072 f32
    const void*  ei = nullptr;
    const float* ea = nullptr;
    for (int i = 0; i < n_in; ++i) {
        if (in_sizes[i] == 2 * NE)   ei = d_in[i];
        else if (in_sizes[i] == NE)  ea = (const float*)d_in[i];
    }
    float* out = (float*)d_out;
    if (!ei || !ea) { ei = d_in[1]; ea = (const float*)d_in[2]; }  // fallback

    detect_kernel<<<1, 256>>>(ei);
    zero_A_kernel<<<(NN * (size_t)NN / 4) / 256, 256>>>();
    scatter_A_kernel<<<NE / 256, 256>>>(ei, ea);
    spmm_kernel<0><<<NN, 256>>>(nullptr);   // g_M2 = thr(A @ A)
    spmm_kernel<1><<<NN, 256>>>(out);       // out = .24A + .144M2 + .0864 thr(A@M2)
    scatter_P0_kernel<<<NE / 256, 256>>>(out, ei);  // += 0.4 per edge (theta0*P0)
}